// round 6
// baseline (speedup 1.0000x reference)
#include <cuda_runtime.h>
#include <cstdint>

// ---------------------------------------------------------------------------
// FTLayer fused kernel, fp32 with packed f32x2 FMA (sm_103a).
//
// Shapes: B=4, A=512, N=128, F=256 (n_in=n_factors=n_out=256)
// Inputs (metadata order):
//  0 x          (B,A,256) f32
//  1 r_ij       (B,A,128) f32
//  2 pairwise_mask (unused by reference)
//  3 in2f_w     (256,256) f32
//  4 in2f_b     (256)     f32
//  5 f2out_w    (256,256) f32
//  6 f2out_b    (256)     f32
//  7 fw1        (1,256)   f32
//  8 fb1        (256)     f32
//  9 fw2        (256,256) f32
// 10 fb2        (256)     f32
// 11 neighbors  (B,A,128) int32  <-- JAX x64-disabled: jnp.int64 request
//                                    silently materializes as int32
// Output: (B,A,128,256) f32
// ---------------------------------------------------------------------------

#define Bv 4
#define Av 512
#define Nv 128
#define Fv 256
#define ROWS_TOTAL (Bv * Av * Nv)   // 262144 pair-rows
#define TILE 64                     // rows per block (divides N=128)
#define HTS 68                      // padded stride for transposed h/y tile (16B aligned)

// Scratch: facts = x @ in2f_w + in2f_b   (B*A, 256) = 2 MB, L2-resident
__device__ float g_facts[Bv * Av * Fv];

// ---- packed f32x2 helpers --------------------------------------------------
__device__ __forceinline__ unsigned long long pack2(float lo, float hi) {
    unsigned long long d;
    asm("mov.b64 %0, {%1, %2};" : "=l"(d) : "f"(lo), "f"(hi));
    return d;
}
__device__ __forceinline__ float2 unpack2(unsigned long long v) {
    float2 r;
    asm("mov.b64 {%0, %1}, %2;" : "=f"(r.x), "=f"(r.y) : "l"(v));
    return r;
}
__device__ __forceinline__ unsigned long long fma2(unsigned long long a,
                                                   unsigned long long b,
                                                   unsigned long long c) {
    unsigned long long d;
    asm("fma.rn.f32x2 %0, %1, %2, %3;" : "=l"(d) : "l"(a), "l"(b), "l"(c));
    return d;
}

// shifted softplus: softplus(v) - ln(2), stable form matching jax.nn.softplus
__device__ __forceinline__ float sspf(float v) {
    float a = fabsf(v);
    return fmaxf(v, 0.0f) + log1pf(__expf(-a)) - 0.6931471824645996f;
}

// ---------------------------------------------------------------------------
// Kernel 1: facts = x @ in2f_w + in2f_b.  16 rows/block, 128 blocks, 256 thr.
// ---------------------------------------------------------------------------
__global__ __launch_bounds__(256) void facts_kernel(
    const float* __restrict__ x, const float* __restrict__ w,
    const float* __restrict__ b) {
    __shared__ float xs[16][Fv];
    const int t = threadIdx.x;
    const int r0 = blockIdx.x * 16;
    #pragma unroll
    for (int m = 0; m < 16; m++) xs[m][t] = x[(r0 + m) * Fv + t];
    __syncthreads();

    float acc[16];
    const float bias = b[t];
    #pragma unroll
    for (int m = 0; m < 16; m++) acc[m] = bias;

    for (int k4 = 0; k4 < Fv / 4; k4++) {
        const float w0 = w[(4 * k4 + 0) * Fv + t];
        const float w1 = w[(4 * k4 + 1) * Fv + t];
        const float w2 = w[(4 * k4 + 2) * Fv + t];
        const float w3 = w[(4 * k4 + 3) * Fv + t];
        #pragma unroll
        for (int m = 0; m < 16; m++) {
            float4 xv = *reinterpret_cast<const float4*>(&xs[m][4 * k4]);
            acc[m] = fmaf(xv.x, w0, acc[m]);
            acc[m] = fmaf(xv.y, w1, acc[m]);
            acc[m] = fmaf(xv.z, w2, acc[m]);
            acc[m] = fmaf(xv.w, w3, acc[m]);
        }
    }
    #pragma unroll
    for (int m = 0; m < 16; m++) g_facts[(r0 + m) * Fv + t] = acc[m];
}

// ---------------------------------------------------------------------------
// Kernel 2: fused main kernel. One block = 64 pair-rows x 256 cols.
//   h = ssp(r*fw1+fb1); W = h@fw2+fb2; y = xi*W*xj; out = ssp(y@f2out_w+f2out_b)
// Per-thread: owns one column t; 64 rows packed as 32 f32x2 accumulators.
// smem ~70 KB -> 2 CTAs/SM.
// ---------------------------------------------------------------------------
__global__ __launch_bounds__(256, 2) void ftlayer_main_kernel(
    const float* __restrict__ r_ij,
    const int* __restrict__ neighbors,
    const float* __restrict__ fw1, const float* __restrict__ fb1,
    const float* __restrict__ fw2, const float* __restrict__ fb2,
    const float* __restrict__ f2w, const float* __restrict__ f2b,
    float* __restrict__ out) {
    extern __shared__ float sm[];
    float* hT  = sm;                          // [256][HTS]  transposed h, later y
    float* r_s = sm + Fv * HTS;               // [TILE]
    int*   rjs = reinterpret_cast<int*>(r_s + TILE);  // [TILE]

    const int t = threadIdx.x;
    const int row0 = blockIdx.x * TILE;       // global pair-row base
    const int ba = row0 >> 7;                 // (b*A + a), since N=128
    const int bbase = (ba >> 9) << 9;         // b*A

    if (t < TILE) {
        int j = neighbors[row0 + t];
        j = min(max(j, 0), Av - 1);           // defensive clamp (dtype safety)
        rjs[t] = bbase + j;
        r_s[t] = r_ij[row0 + t];
    }
    __syncthreads();

    const float xi = g_facts[ba * Fv + t];

    // h transposed: thread t handles k=t for all 64 rows
    {
        const float w1v = fw1[t];
        const float b1v = fb1[t];
        float* hrow = hT + t * HTS;
        #pragma unroll 4
        for (int m = 0; m < TILE; m++)
            hrow[m] = sspf(fmaf(r_s[m], w1v, b1v));
    }
    __syncthreads();

    unsigned long long acc[TILE / 2];

    // ---- GEMM1: W[:,t] = h @ fw2[:,t] + fb2[t] ----
    {
        const float b2 = fb2[t];
        const unsigned long long bp = pack2(b2, b2);
        #pragma unroll
        for (int q = 0; q < TILE / 2; q++) acc[q] = bp;
    }
    #pragma unroll 2
    for (int k = 0; k < Fv; k++) {
        const float w = fw2[k * Fv + t];
        const unsigned long long wd = pack2(w, w);
        const ulonglong2* hp = reinterpret_cast<const ulonglong2*>(hT + k * HTS);
        #pragma unroll
        for (int j4 = 0; j4 < TILE / 4; j4++) {
            ulonglong2 hv = hp[j4];                 // rows 4j4..4j4+3 (broadcast LDS.128)
            acc[2 * j4]     = fma2(hv.x, wd, acc[2 * j4]);
            acc[2 * j4 + 1] = fma2(hv.y, wd, acc[2 * j4 + 1]);
        }
    }

    // epilogue 1: y = xi * W * xj  (xj read directly from L2-resident g_facts,
    // coalesced across threads), then re-transposed into hT
    #pragma unroll 8
    for (int q = 0; q < TILE / 2; q++) {
        float xj0 = g_facts[rjs[2 * q]     * Fv + t];
        float xj1 = g_facts[rjs[2 * q + 1] * Fv + t];
        float2 s = unpack2(acc[q]);
        acc[q] = pack2(xi * s.x * xj0, xi * s.y * xj1);
    }
    __syncthreads();   // everyone done reading hT
    {
        unsigned long long* yrow = reinterpret_cast<unsigned long long*>(hT + t * HTS);
        #pragma unroll
        for (int q = 0; q < TILE / 2; q++) yrow[q] = acc[q];
    }
    __syncthreads();

    // ---- GEMM2: out[:,t] = y @ f2out_w[:,t] + f2out_b[t] ----
    {
        const float bo = f2b[t];
        const unsigned long long bp = pack2(bo, bo);
        #pragma unroll
        for (int q = 0; q < TILE / 2; q++) acc[q] = bp;
    }
    #pragma unroll 2
    for (int k = 0; k < Fv; k++) {
        const float w = f2w[k * Fv + t];
        const unsigned long long wd = pack2(w, w);
        const ulonglong2* yp = reinterpret_cast<const ulonglong2*>(hT + k * HTS);
        #pragma unroll
        for (int j4 = 0; j4 < TILE / 4; j4++) {
            ulonglong2 yv = yp[j4];
            acc[2 * j4]     = fma2(yv.x, wd, acc[2 * j4]);
            acc[2 * j4 + 1] = fma2(yv.y, wd, acc[2 * j4 + 1]);
        }
    }

    // epilogue 2: ssp + store (coalesced per row)
    float* op = out + (long long)row0 * Fv + t;
    #pragma unroll
    for (int q = 0; q < TILE / 2; q++) {
        float2 s = unpack2(acc[q]);
        op[(long long)(2 * q) * Fv]     = sspf(s.x);
        op[(long long)(2 * q + 1) * Fv] = sspf(s.y);
    }
}

// ---------------------------------------------------------------------------
extern "C" void kernel_launch(void* const* d_in, const int* in_sizes, int n_in,
                              void* d_out, int out_size) {
    const float* x      = (const float*)d_in[0];
    const float* r_ij   = (const float*)d_in[1];
    // d_in[2] pairwise_mask: unused by reference
    const float* in2f_w = (const float*)d_in[3];
    const float* in2f_b = (const float*)d_in[4];
    const float* f2w    = (const float*)d_in[5];
    const float* f2b    = (const float*)d_in[6];
    const float* fw1    = (const float*)d_in[7];
    const float* fb1    = (const float*)d_in[8];
    const float* fw2    = (const float*)d_in[9];
    const float* fb2    = (const float*)d_in[10];
    const int*   nbr    = (const int*)d_in[11];   // int32 (JAX x64 disabled)
    float* out = (float*)d_out;

    const size_t smem_bytes =
        (size_t)(Fv * HTS + TILE) * sizeof(float) + TILE * sizeof(int);

    // idempotent, host-side only: safe under graph capture
    cudaFuncSetAttribute(ftlayer_main_kernel,
                         cudaFuncAttributeMaxDynamicSharedMemorySize,
                         (int)smem_bytes);

    facts_kernel<<<(Bv * Av) / 16, 256>>>(x, in2f_w, in2f_b);
    ftlayer_main_kernel<<<ROWS_TOTAL / TILE, 256, smem_bytes>>>(
        r_ij, nbr, fw1, fb1, fw2, fb2, f2w, f2b, out);
}

// round 7
// speedup vs baseline: 1.3921x; 1.3921x over previous
#include <cuda_runtime.h>
#include <cstdint>

// ---------------------------------------------------------------------------
// FTLayer fused kernel, fp32 with packed f32x2 FMA + 2D register tiling.
// sm_103a. Shapes: B=4, A=512, N=128, F=256.
//
// neighbors is int32 (JAX x64 disabled silently downgrades jnp.int64).
// Output: (B,A,128,256) f32
// ---------------------------------------------------------------------------

#define Bv 4
#define Av 512
#define Nv 128
#define Fv 256
#define ROWS_TOTAL (Bv * Av * Nv)   // 262144 pair-rows
#define TILE 64                     // rows per block
#define HTS 68                      // padded stride for transposed h/y tile (16B aligned)

// Scratch: facts = x @ in2f_w + in2f_b   (B*A, 256) = 2 MB, L2-resident
__device__ float g_facts[Bv * Av * Fv];

// ---- packed f32x2 helpers --------------------------------------------------
__device__ __forceinline__ unsigned long long pack2(float lo, float hi) {
    unsigned long long d;
    asm("mov.b64 %0, {%1, %2};" : "=l"(d) : "f"(lo), "f"(hi));
    return d;
}
__device__ __forceinline__ float2 unpack2(unsigned long long v) {
    float2 r;
    asm("mov.b64 {%0, %1}, %2;" : "=f"(r.x), "=f"(r.y) : "l"(v));
    return r;
}
__device__ __forceinline__ unsigned long long fma2(unsigned long long a,
                                                   unsigned long long b,
                                                   unsigned long long c) {
    unsigned long long d;
    asm("fma.rn.f32x2 %0, %1, %2, %3;" : "=l"(d) : "l"(a), "l"(b), "l"(c));
    return d;
}

// shifted softplus: softplus(v) - ln(2), stable form matching jax.nn.softplus
__device__ __forceinline__ float sspf(float v) {
    float a = fabsf(v);
    return fmaxf(v, 0.0f) + log1pf(__expf(-a)) - 0.6931471824645996f;
}

// ---------------------------------------------------------------------------
// Kernel 1: facts = x @ in2f_w + in2f_b.  16 rows/block, 128 blocks, 256 thr.
// ---------------------------------------------------------------------------
__global__ __launch_bounds__(256) void facts_kernel(
    const float* __restrict__ x, const float* __restrict__ w,
    const float* __restrict__ b) {
    __shared__ float xs[16][Fv];
    const int t = threadIdx.x;
    const int r0 = blockIdx.x * 16;
    #pragma unroll
    for (int m = 0; m < 16; m++) xs[m][t] = x[(r0 + m) * Fv + t];
    __syncthreads();

    float acc[16];
    const float bias = b[t];
    #pragma unroll
    for (int m = 0; m < 16; m++) acc[m] = bias;

    for (int k4 = 0; k4 < Fv / 4; k4++) {
        const float w0 = w[(4 * k4 + 0) * Fv + t];
        const float w1 = w[(4 * k4 + 1) * Fv + t];
        const float w2 = w[(4 * k4 + 2) * Fv + t];
        const float w3 = w[(4 * k4 + 3) * Fv + t];
        #pragma unroll
        for (int m = 0; m < 16; m++) {
            float4 xv = *reinterpret_cast<const float4*>(&xs[m][4 * k4]);
            acc[m] = fmaf(xv.x, w0, acc[m]);
            acc[m] = fmaf(xv.y, w1, acc[m]);
            acc[m] = fmaf(xv.z, w2, acc[m]);
            acc[m] = fmaf(xv.w, w3, acc[m]);
        }
    }
    #pragma unroll
    for (int m = 0; m < 16; m++) g_facts[(r0 + m) * Fv + t] = acc[m];
}

// ---------------------------------------------------------------------------
// Kernel 2: fused main kernel. Block = 64 pair-rows x 256 cols, 256 threads.
// Thread tile: 16 rows x 4 cols (rg = tid>>6, cg = tid&63).
// Per k: 4 LDS.128 (broadcast h rows) + 1 LDG.128 (weight) + 32 FFMA2.
// ---------------------------------------------------------------------------
__global__ __launch_bounds__(256, 2) void ftlayer_main_kernel(
    const float* __restrict__ r_ij,
    const int* __restrict__ neighbors,
    const float* __restrict__ fw1, const float* __restrict__ fb1,
    const float* __restrict__ fw2, const float* __restrict__ fb2,
    const float* __restrict__ f2w, const float* __restrict__ f2b,
    float* __restrict__ out) {
    extern __shared__ float sm[];
    float* hT  = sm;                          // [256][HTS]  transposed h, later y
    float* r_s = sm + Fv * HTS;               // [TILE]
    int*   rjs = reinterpret_cast<int*>(r_s + TILE);  // [TILE]

    const int t   = threadIdx.x;
    const int rg  = t >> 6;                   // 0..3   row group
    const int cg  = t & 63;                   // 0..63  col group
    const int r0t = rg * 16;                  // thread's first row in tile
    const int c0  = cg * 4;                   // thread's first col

    const int row0 = blockIdx.x * TILE;       // global pair-row base
    const int ba = row0 >> 7;                 // (b*A + a), since N=128
    const int bbase = (ba >> 9) << 9;         // b*A

    if (t < TILE) {
        int j = neighbors[row0 + t];
        j = min(max(j, 0), Av - 1);           // defensive clamp
        rjs[t] = bbase + j;
        r_s[t] = r_ij[row0 + t];
    }
    __syncthreads();

    // h transposed: thread t handles k=t for all 64 rows
    {
        const float w1v = fw1[t];
        const float b1v = fb1[t];
        float* hrow = hT + t * HTS;
        #pragma unroll 4
        for (int m = 0; m < TILE; m++)
            hrow[m] = sspf(fmaf(r_s[m], w1v, b1v));
    }
    __syncthreads();

    unsigned long long acc[32];               // [c][q]: 4 cols x 8 row-pairs

    // ---- GEMM1: W = h @ fw2 + fb2 (thread computes 16x4 tile) ----
    {
        const float4 b4 = *reinterpret_cast<const float4*>(fb2 + c0);
        const float bb[4] = {b4.x, b4.y, b4.z, b4.w};
        #pragma unroll
        for (int c = 0; c < 4; c++) {
            const unsigned long long bp = pack2(bb[c], bb[c]);
            #pragma unroll
            for (int q = 0; q < 8; q++) acc[c * 8 + q] = bp;
        }
    }
    {
        const float4* wp = reinterpret_cast<const float4*>(fw2 + c0);
        const float* hbase = hT + r0t;
        #pragma unroll 2
        for (int k = 0; k < Fv; k++) {
            const float4 w4 = __ldg(wp + k * (Fv / 4));
            const ulonglong2* hp =
                reinterpret_cast<const ulonglong2*>(hbase + k * HTS);
            ulonglong2 ha = hp[0], hb = hp[1], hc = hp[2], hd = hp[3];
            const unsigned long long h[8] = {ha.x, ha.y, hb.x, hb.y,
                                             hc.x, hc.y, hd.x, hd.y};
            const float wv[4] = {w4.x, w4.y, w4.z, w4.w};
            #pragma unroll
            for (int c = 0; c < 4; c++) {
                const unsigned long long wd = pack2(wv[c], wv[c]);
                #pragma unroll
                for (int q = 0; q < 8; q++)
                    acc[c * 8 + q] = fma2(h[q], wd, acc[c * 8 + q]);
            }
        }
    }

    // ---- epilogue 1: y = xi * W * xj ----
    {
        const float4 xi4 = *reinterpret_cast<const float4*>(g_facts + ba * Fv + c0);
        const float xiv[4] = {xi4.x, xi4.y, xi4.z, xi4.w};
        #pragma unroll
        for (int q = 0; q < 8; q++) {
            const int ra = r0t + 2 * q, rb = ra + 1;
            const float4 xa = *reinterpret_cast<const float4*>(g_facts + rjs[ra] * Fv + c0);
            const float4 xb = *reinterpret_cast<const float4*>(g_facts + rjs[rb] * Fv + c0);
            const float xav[4] = {xa.x, xa.y, xa.z, xa.w};
            const float xbv[4] = {xb.x, xb.y, xb.z, xb.w};
            #pragma unroll
            for (int c = 0; c < 4; c++) {
                float2 s = unpack2(acc[c * 8 + q]);
                acc[c * 8 + q] = pack2(xiv[c] * s.x * xav[c],
                                       xiv[c] * s.y * xbv[c]);
            }
        }
    }
    __syncthreads();   // all reads of hT (GEMM1) done
    // write y transposed: yT[col][row]
    {
        #pragma unroll
        for (int c = 0; c < 4; c++) {
            unsigned long long* yrow =
                reinterpret_cast<unsigned long long*>(hT + (c0 + c) * HTS + r0t);
            #pragma unroll
            for (int q = 0; q < 8; q++) yrow[q] = acc[c * 8 + q];
        }
    }
    __syncthreads();

    // ---- GEMM2: out = ssp(y @ f2out_w + f2out_b) ----
    {
        const float4 b4 = *reinterpret_cast<const float4*>(f2b + c0);
        const float bb[4] = {b4.x, b4.y, b4.z, b4.w};
        #pragma unroll
        for (int c = 0; c < 4; c++) {
            const unsigned long long bp = pack2(bb[c], bb[c]);
            #pragma unroll
            for (int q = 0; q < 8; q++) acc[c * 8 + q] = bp;
        }
    }
    {
        const float4* wp = reinterpret_cast<const float4*>(f2w + c0);
        const float* ybase = hT + r0t;
        #pragma unroll 2
        for (int k = 0; k < Fv; k++) {
            const float4 w4 = __ldg(wp + k * (Fv / 4));
            const ulonglong2* yp =
                reinterpret_cast<const ulonglong2*>(ybase + k * HTS);
            ulonglong2 ya = yp[0], yb = yp[1], yc = yp[2], yd = yp[3];
            const unsigned long long y[8] = {ya.x, ya.y, yb.x, yb.y,
                                             yc.x, yc.y, yd.x, yd.y};
            const float wv[4] = {w4.x, w4.y, w4.z, w4.w};
            #pragma unroll
            for (int c = 0; c < 4; c++) {
                const unsigned long long wd = pack2(wv[c], wv[c]);
                #pragma unroll
                for (int q = 0; q < 8; q++)
                    acc[c * 8 + q] = fma2(y[q], wd, acc[c * 8 + q]);
            }
        }
    }

    // ---- epilogue 2: ssp + coalesced float4 stores ----
    {
        float* ob = out + (long long)row0 * Fv + c0;
        #pragma unroll
        for (int q = 0; q < 8; q++) {
            const int ra = r0t + 2 * q, rb = ra + 1;
            float2 s0 = unpack2(acc[0 * 8 + q]);
            float2 s1 = unpack2(acc[1 * 8 + q]);
            float2 s2 = unpack2(acc[2 * 8 + q]);
            float2 s3 = unpack2(acc[3 * 8 + q]);
            float4 oa = make_float4(sspf(s0.x), sspf(s1.x), sspf(s2.x), sspf(s3.x));
            float4 ob4 = make_float4(sspf(s0.y), sspf(s1.y), sspf(s2.y), sspf(s3.y));
            *reinterpret_cast<float4*>(ob + (long long)ra * Fv) = oa;
            *reinterpret_cast<float4*>(ob + (long long)rb * Fv) = ob4;
        }
    }
}

// ---------------------------------------------------------------------------
extern "C" void kernel_launch(void* const* d_in, const int* in_sizes, int n_in,
                              void* d_out, int out_size) {
    const float* x      = (const float*)d_in[0];
    const float* r_ij   = (const float*)d_in[1];
    // d_in[2] pairwise_mask: unused by reference
    const float* in2f_w = (const float*)d_in[3];
    const float* in2f_b = (const float*)d_in[4];
    const float* f2w    = (const float*)d_in[5];
    const float* f2b    = (const float*)d_in[6];
    const float* fw1    = (const float*)d_in[7];
    const float* fb1    = (const float*)d_in[8];
    const float* fw2    = (const float*)d_in[9];
    const float* fb2    = (const float*)d_in[10];
    const int*   nbr    = (const int*)d_in[11];   // int32 (JAX x64 disabled)
    float* out = (float*)d_out;

    const size_t smem_bytes =
        (size_t)(Fv * HTS + TILE) * sizeof(float) + TILE * sizeof(int);

    cudaFuncSetAttribute(ftlayer_main_kernel,
                         cudaFuncAttributeMaxDynamicSharedMemorySize,
                         (int)smem_bytes);

    facts_kernel<<<(Bv * Av) / 16, 256>>>(x, in2f_w, in2f_b);
    ftlayer_main_kernel<<<ROWS_TOTAL / TILE, 256, smem_bytes>>>(
        r_ij, nbr, fw1, fb1, fw2, fb2, f2w, f2b, out);
}